// round 14
// baseline (speedup 1.0000x reference)
#include <cuda_runtime.h>
#include <cstdint>

#define DI __device__ __forceinline__

// ---- problem constants ----
#define BDIM 4096
#define HDIM 1024
#define KTOT 2048
#define BM 128
#define BN 128
#define BK 32
#define KIT (KTOT / BK)          // 64
#define TILE_B (BM * BK * 4)     // 16384 bytes per operand tile
#define NSTAGE 3
#define SM_A 0
#define SM_B (NSTAGE * TILE_B)
#define SMEM_TOTAL (2 * NSTAGE * TILE_B)   // 98304

// gates scratch (allocation-free rule -> __device__ global, 64 MB)
__device__ float g_G[(size_t)BDIM * 4096];

// ---- PTX helpers (all plain compute_80+, nothing sm_103a-gated) ----
DI uint32_t s2u(const void* p) {
    uint32_t a;
    asm("{ .reg .u64 t; cvta.to.shared.u64 t, %1; cvt.u32.u64 %0, t; }" : "=r"(a) : "l"(p));
    return a;
}
DI void cpa16(uint32_t dst, const void* src) {
    asm volatile("cp.async.cg.shared.global [%0], [%1], 16;" :: "r"(dst), "l"(src) : "memory");
}
DI void cp_commit() { asm volatile("cp.async.commit_group;" ::: "memory"); }
template <int N> DI void cp_wait() { asm volatile("cp.async.wait_group %0;" :: "n"(N) : "memory"); }

DI float ldsf(uint32_t base, int row, int col) {
    // SW128-style XOR swizzle: 16B chunk c at ((c ^ (row&7)) << 4)
    uint32_t addr = base + (uint32_t)row * 128u
                  + (uint32_t)((((col >> 2) ^ (row & 7)) << 4) | ((col & 3) << 2));
    float v;
    asm("ld.shared.f32 %0, [%1];" : "=f"(v) : "r"(addr));
    return v;
}
DI uint32_t tf32r(float f) {
    uint32_t u;
    asm("cvt.rna.tf32.f32 %0, %1;" : "=r"(u) : "f"(f));
    return u;
}
DI void mma8(float* d, const uint32_t* a, const uint32_t* b) {
    asm volatile(
        "mma.sync.aligned.m16n8k8.row.col.f32.tf32.tf32.f32 "
        "{%0,%1,%2,%3}, {%4,%5,%6,%7}, {%8,%9}, {%0,%1,%2,%3};"
        : "+f"(d[0]), "+f"(d[1]), "+f"(d[2]), "+f"(d[3])
        : "r"(a[0]), "r"(a[1]), "r"(a[2]), "r"(a[3]), "r"(b[0]), "r"(b[1]));
}
DI float sigf(float x) { return 1.0f / (1.0f + __expf(-x)); }

// ---- stage loader: A tile (128x32) + B tile (128x32), 16B cp.async chunks ----
DI void load_slab(uint32_t sA, uint32_t sB, const float* Ap, const float* Bp, int tid) {
#pragma unroll
    for (int i = 0; i < 4; i++) {
        int q = tid + i * 256;           // 0..1023 chunks per tile
        int row = q >> 3, c = q & 7;
        uint32_t off = (uint32_t)row * 128u + (uint32_t)((c ^ (row & 7)) << 4);
        cpa16(sA + off, Ap + (size_t)row * 1024 + c * 4);
        cpa16(sB + off, Bp + (size_t)row * 1024 + c * 4);
    }
}

// ---- GEMM: gates[m][j] = sum_k A[m][k] * Wcat[j][k] ----
__global__ void __launch_bounds__(256, 1) gemm_gates(
    const float* __restrict__ x, const float* __restrict__ h,
    const float* __restrict__ Wxi, const float* __restrict__ Wxf,
    const float* __restrict__ Wxg, const float* __restrict__ Wxo,
    const float* __restrict__ Whi, const float* __restrict__ Whf,
    const float* __restrict__ Whg, const float* __restrict__ Who)
{
    extern __shared__ char smem[];
    const uint32_t sb = s2u(smem);
    const int tid = threadIdx.x;
    const int m_base = blockIdx.x * BM;
    const int j_base = blockIdx.y * BN;
    const int gate = j_base >> 10;
    const int n_in_gate = j_base & 1023;
    const float* Wx = gate == 0 ? Wxi : gate == 1 ? Wxf : gate == 2 ? Wxg : Wxo;
    const float* Wh = gate == 0 ? Whi : gate == 1 ? Whf : gate == 2 ? Whg : Who;

    const float* Am = x;   // dummy init; selected per slab below
    (void)Am;

    const int wid = tid >> 5, lane = tid & 31;
    const int wm = wid >> 2, wn = wid & 3;          // 2x4 warp grid
    const int gq = lane >> 2, tq = lane & 3;

    float acc[4][4][4];
#pragma unroll
    for (int a = 0; a < 4; a++)
#pragma unroll
        for (int b = 0; b < 4; b++)
#pragma unroll
            for (int c = 0; c < 4; c++) acc[a][b][c] = 0.0f;

    // prologue: stages 0..NSTAGE-2
#pragma unroll
    for (int s = 0; s < NSTAGE - 1; s++) {
        const int k0 = s * BK;
        const float* Ap = (k0 < 1024) ? x + (size_t)m_base * 1024 + k0
                                      : h + (size_t)m_base * 1024 + (k0 - 1024);
        const float* Bp = (k0 < 1024) ? Wx + (size_t)n_in_gate * 1024 + k0
                                      : Wh + (size_t)n_in_gate * 1024 + (k0 - 1024);
        load_slab(sb + SM_A + s * TILE_B, sb + SM_B + s * TILE_B, Ap, Bp, tid);
        cp_commit();
    }

    for (int kk = 0; kk < KIT; kk++) {
        const int s = kk % NSTAGE;
        if (kk == KIT - 1) cp_wait<0>(); else cp_wait<1>();
        __syncthreads();

        const int kn = kk + NSTAGE - 1;
        if (kn < KIT) {
            const int sn = kn % NSTAGE;
            const int k0 = kn * BK;
            const float* Ap = (k0 < 1024) ? x + (size_t)m_base * 1024 + k0
                                          : h + (size_t)m_base * 1024 + (k0 - 1024);
            const float* Bp = (k0 < 1024) ? Wx + (size_t)n_in_gate * 1024 + k0
                                          : Wh + (size_t)n_in_gate * 1024 + (k0 - 1024);
            load_slab(sb + SM_A + sn * TILE_B, sb + SM_B + sn * TILE_B, Ap, Bp, tid);
            cp_commit();
        }

        const uint32_t sA = sb + SM_A + s * TILE_B;
        const uint32_t sB = sb + SM_B + s * TILE_B;
#pragma unroll
        for (int ks = 0; ks < 4; ks++) {
            uint32_t a[4][4], b[4][2];
#pragma unroll
            for (int mt = 0; mt < 4; mt++) {
                const int row = wm * 64 + mt * 16 + gq;
                const int col = ks * 8 + tq;
                a[mt][0] = tf32r(ldsf(sA, row,     col));
                a[mt][1] = tf32r(ldsf(sA, row + 8, col));
                a[mt][2] = tf32r(ldsf(sA, row,     col + 4));
                a[mt][3] = tf32r(ldsf(sA, row + 8, col + 4));
            }
#pragma unroll
            for (int nt = 0; nt < 4; nt++) {
                const int n = wn * 32 + nt * 8 + gq;
                const int kc = ks * 8 + tq;
                b[nt][0] = tf32r(ldsf(sB, n, kc));
                b[nt][1] = tf32r(ldsf(sB, n, kc + 4));
            }
#pragma unroll
            for (int mt = 0; mt < 4; mt++)
#pragma unroll
                for (int nt = 0; nt < 4; nt++)
                    mma8(acc[mt][nt], a[mt], b[nt]);
        }
        __syncthreads();
    }

    // store accumulators -> g_G (float2 per lane, 32B-sector aligned)
#pragma unroll
    for (int mt = 0; mt < 4; mt++) {
        const int row = m_base + wm * 64 + mt * 16 + gq;
#pragma unroll
        for (int nt = 0; nt < 4; nt++) {
            const int col = j_base + wn * 32 + nt * 8 + 2 * tq;
            *(float2*)&g_G[(size_t)row * 4096 + col] =
                make_float2(acc[mt][nt][0], acc[mt][nt][1]);
            *(float2*)&g_G[(size_t)(row + 8) * 4096 + col] =
                make_float2(acc[mt][nt][2], acc[mt][nt][3]);
        }
    }
}

// ---- epilogue: bias + activations + c/h update, writes 6 planes ----
__global__ void __launch_bounds__(256) lstm_epilogue(
    const float* __restrict__ c_prev,
    const float* __restrict__ bi, const float* __restrict__ bf,
    const float* __restrict__ bg, const float* __restrict__ bo,
    float* __restrict__ out, int nplanes)
{
    const int idx = blockIdx.x * 256 + threadIdx.x;   // float4 index over (m, h/4)
    const int m = idx >> 8;
    const int hh = (idx & 255) << 2;
    const float* gr = g_G + (size_t)m * 4096;

    float4 zi = *(const float4*)&gr[hh];
    float4 zf = *(const float4*)&gr[1024 + hh];
    float4 zg = *(const float4*)&gr[2048 + hh];
    float4 zo = *(const float4*)&gr[3072 + hh];
    float4 vbi = *(const float4*)&bi[hh];
    float4 vbf = *(const float4*)&bf[hh];
    float4 vbg = *(const float4*)&bg[hh];
    float4 vbo = *(const float4*)&bo[hh];
    float4 cp = *(const float4*)&c_prev[(size_t)m * HDIM + hh];

    float r[6][4];
    const float* pzi = &zi.x; const float* pzf = &zf.x;
    const float* pzg = &zg.x; const float* pzo = &zo.x;
    const float* pbi = &vbi.x; const float* pbf = &vbf.x;
    const float* pbg = &vbg.x; const float* pbo = &vbo.x;
    const float* pcp = &cp.x;
#pragma unroll
    for (int j = 0; j < 4; j++) {
        float vi = sigf(pzi[j] + pbi[j]);
        float vf = sigf(pzf[j] + pbf[j]);
        float vg = tanhf(pzg[j] + pbg[j]);
        float vo = sigf(pzo[j] + pbo[j]);
        float cc = vf * pcp[j] + vi * vg;
        r[0][j] = vo * tanhf(cc);
        r[1][j] = cc;
        r[2][j] = vi; r[3][j] = vf; r[4][j] = vg; r[5][j] = vo;
    }
    const size_t P = (size_t)BDIM * HDIM;
    float* o = out + (size_t)m * HDIM + hh;
#pragma unroll
    for (int pl = 0; pl < 6; pl++)
        if (pl < nplanes)
            *(float4*)(o + (size_t)pl * P) = *(const float4*)r[pl];
}

extern "C" void kernel_launch(void* const* d_in, const int* in_sizes, int n_in,
                              void* d_out, int out_size) {
    const float* x   = (const float*)d_in[0];
    const float* h   = (const float*)d_in[1];
    const float* c   = (const float*)d_in[2];
    const float* Wii = (const float*)d_in[3];  const float* bii = (const float*)d_in[4];
    const float* Wif = (const float*)d_in[5];  const float* bif = (const float*)d_in[6];
    const float* Wig = (const float*)d_in[7];  const float* big = (const float*)d_in[8];
    const float* Wio = (const float*)d_in[9];  const float* bio = (const float*)d_in[10];
    const float* Whi = (const float*)d_in[11]; const float* Whf = (const float*)d_in[12];
    const float* Whg = (const float*)d_in[13]; const float* Who = (const float*)d_in[14];

    static int smem_set = 0;
    if (!smem_set) {
        cudaFuncSetAttribute(gemm_gates, cudaFuncAttributeMaxDynamicSharedMemorySize, SMEM_TOTAL);
        smem_set = 1;
    }

    dim3 grid(BDIM / BM, 4096 / BN);   // (32, 32)
    gemm_gates<<<grid, 256, SMEM_TOTAL>>>(x, h, Wii, Wif, Wig, Wio, Whi, Whf, Whg, Who);

    int np = out_size / (BDIM * HDIM);
    if (np > 6) np = 6;
    if (np < 1) np = 1;
    lstm_epilogue<<<(BDIM * HDIM / 4) / 256, 256>>>(c, bii, bif, big, bio, (float*)d_out, np);
}

// round 15
// speedup vs baseline: 1.1536x; 1.1536x over previous
#include <cuda_runtime.h>
#include <cstdint>

#define DI __device__ __forceinline__

// ---- problem constants ----
#define BDIM 4096
#define HDIM 1024
#define KIT  64                   // 2048 / 32
#define TILE_B 16384              // 128 rows x 32 k x 4B
#define NSTAGE 3
#define SMEM_TOTAL (2 * NSTAGE * TILE_B)   // 98304

// ---- device scratch (allocation-free rule) ----
__device__ float g_G[(size_t)BDIM * 4096];                    // gates, 64 MB
__device__ uint4 g_A[(size_t)BDIM * 2048 / 4];                // permuted tf32 [x|h], 32 MB
__device__ uint4 g_B[(size_t)4096 * 2048 / 4];                // permuted tf32 Wcat,  32 MB

// ---- PTX helpers (plain compute_80+, nothing sm_103a-gated) ----
DI uint32_t s2u(const void* p) {
    uint32_t a;
    asm("{ .reg .u64 t; cvta.to.shared.u64 t, %1; cvt.u32.u64 %0, t; }" : "=r"(a) : "l"(p));
    return a;
}
DI void cpa16(uint32_t dst, const void* src) {
    asm volatile("cp.async.cg.shared.global [%0], [%1], 16;" :: "r"(dst), "l"(src) : "memory");
}
DI void cp_commit() { asm volatile("cp.async.commit_group;" ::: "memory"); }
template <int N> DI void cp_wait() { asm volatile("cp.async.wait_group %0;" :: "n"(N) : "memory"); }
DI uint32_t tf32r(float f) {
    uint32_t u;
    asm("cvt.rna.tf32.f32 %0, %1;" : "=r"(u) : "f"(f));
    return u;
}
DI uint4 lds128(uint32_t a) {
    uint4 v;
    asm volatile("ld.shared.v4.b32 {%0,%1,%2,%3}, [%4];"
                 : "=r"(v.x), "=r"(v.y), "=r"(v.z), "=r"(v.w) : "r"(a));
    return v;
}
DI void mma8(float* d, uint4 a, uint32_t b0, uint32_t b1) {
    asm volatile(
        "mma.sync.aligned.m16n8k8.row.col.f32.tf32.tf32.f32 "
        "{%0,%1,%2,%3}, {%4,%5,%6,%7}, {%8,%9}, {%0,%1,%2,%3};"
        : "+f"(d[0]), "+f"(d[1]), "+f"(d[2]), "+f"(d[3])
        : "r"(a.x), "r"(a.y), "r"(a.z), "r"(a.w), "r"(b0), "r"(b1));
}
DI float sigf(float x) { return 1.0f / (1.0f + __expf(-x)); }

// =====================================================================
// Pack kernels: tf32-round + concat + permute into mma fragment order.
// Output group index idx (16B = 4 fragment values for one lane):
//   idx = ((((tile*64 + kslab)*8 + i)*4 + ks)*32 + lane)
//   lane -> gq=lane>>2, tq=lane&3 ; subtile rows r0=tile*128+i*16, cols c0=kslab*32+ks*8
//   slots: v0=(r0+gq, c0+tq) v1=(r0+8+gq, c0+tq) v2=(r0+gq, c0+tq+4) v3=(r0+8+gq, c0+tq+4)
// =====================================================================
__global__ void __launch_bounds__(256) pack_A(const float* __restrict__ x,
                                              const float* __restrict__ h) {
    int idx = blockIdx.x * 256 + threadIdx.x;       // 0 .. 2M-1
    int lane = idx & 31;
    int ks   = (idx >> 5) & 3;
    int i    = (idx >> 7) & 7;
    int ksl  = (idx >> 10) & 63;
    int mt   = idx >> 16;
    int gq = lane >> 2, tq = lane & 3;
    int r = mt * 128 + i * 16 + gq;
    int c = ksl * 32 + ks * 8 + tq;
    const float* src = (c < 1024) ? x : h;
    int cc = (c < 1024) ? c : c - 1024;
    uint4 o;
    o.x = tf32r(src[(size_t)r * 1024 + cc]);
    o.y = tf32r(src[(size_t)(r + 8) * 1024 + cc]);
    o.z = tf32r(src[(size_t)r * 1024 + cc + 4]);
    o.w = tf32r(src[(size_t)(r + 8) * 1024 + cc + 4]);
    g_A[idx] = o;
}

__global__ void __launch_bounds__(256) pack_B(
    const float* __restrict__ Wxi, const float* __restrict__ Wxf,
    const float* __restrict__ Wxg, const float* __restrict__ Wxo,
    const float* __restrict__ Whi, const float* __restrict__ Whf,
    const float* __restrict__ Whg, const float* __restrict__ Who) {
    int idx = blockIdx.x * 256 + threadIdx.x;       // 0 .. 2M-1
    int lane = idx & 31;
    int ks   = (idx >> 5) & 3;
    int i    = (idx >> 7) & 7;
    int ksl  = (idx >> 10) & 63;
    int jt   = idx >> 16;                            // 0..31
    int gq = lane >> 2, tq = lane & 3;
    int j = jt * 128 + i * 16 + gq;                  // Wcat row (gate*1024 + h)
    int gate = j >> 10, hh = j & 1023;
    int c = ksl * 32 + ks * 8 + tq;
    const float* W;
    int cc;
    if (c < 1024) {
        W = (gate == 0) ? Wxi : (gate == 1) ? Wxf : (gate == 2) ? Wxg : Wxo;
        cc = c;
    } else {
        W = (gate == 0) ? Whi : (gate == 1) ? Whf : (gate == 2) ? Whg : Who;
        cc = c - 1024;
    }
    uint4 o;
    o.x = tf32r(W[(size_t)hh * 1024 + cc]);
    o.y = tf32r(W[(size_t)(hh + 8) * 1024 + cc]);
    o.z = tf32r(W[(size_t)hh * 1024 + cc + 4]);
    o.w = tf32r(W[(size_t)(hh + 8) * 1024 + cc + 4]);
    g_B[idx] = o;
}

// ---- stage loader: contiguous 16KB tile -> contiguous smem (no swizzle needed) ----
DI void load_stage(uint32_t sA, uint32_t sB, const uint4* Ag, const uint4* Bg, int tid) {
#pragma unroll
    for (int i = 0; i < 4; i++) {
        int q = tid + i * 256;
        cpa16(sA + (uint32_t)q * 16u, Ag + q);
        cpa16(sB + (uint32_t)q * 16u, Bg + q);
    }
}

// =====================================================================
// GEMM: gates[m][j] = sum_k A[m][k] * Wcat[j][k]
// 128x128x32 CTA tile, 2x4 warps (warp 64x32), fragment-ordered smem.
// =====================================================================
__global__ void __launch_bounds__(256) gemm_gates() {
    extern __shared__ char smem[];
    const uint32_t sb = s2u(smem);
    const int tid = threadIdx.x;
    const int wid = tid >> 5, lane = tid & 31;
    const int wm = wid >> 2, wn = wid & 3;
    const int gq = lane >> 2, tq = lane & 3;

    const uint4* Abase = g_A + (size_t)blockIdx.x * 64 * 1024;  // 64 k-slabs x 1024 uint4
    const uint4* Bbase = g_B + (size_t)blockIdx.y * 64 * 1024;

    float acc[4][4][4];
#pragma unroll
    for (int a = 0; a < 4; a++)
#pragma unroll
        for (int b = 0; b < 4; b++)
#pragma unroll
            for (int c = 0; c < 4; c++) acc[a][b][c] = 0.0f;

    // prologue: stages 0,1
#pragma unroll
    for (int s = 0; s < NSTAGE - 1; s++) {
        load_stage(sb + s * TILE_B, sb + (NSTAGE + s) * TILE_B,
                   Abase + s * 1024, Bbase + s * 1024, tid);
        cp_commit();
    }

    for (int kk = 0; kk < KIT; kk++) {
        const int s = kk % NSTAGE;
        if (kk >= KIT - 2) cp_wait<0>(); else cp_wait<1>();
        __syncthreads();

        const int kn = kk + NSTAGE - 1;
        if (kn < KIT) {
            const int sn = kn % NSTAGE;
            load_stage(sb + sn * TILE_B, sb + (NSTAGE + sn) * TILE_B,
                       Abase + kn * 1024, Bbase + kn * 1024, tid);
            cp_commit();
        }

        const uint32_t sA = sb + s * TILE_B + (uint32_t)lane * 16u;
        const uint32_t sB = sb + (NSTAGE + s) * TILE_B + (uint32_t)lane * 16u;
#pragma unroll
        for (int ks = 0; ks < 4; ks++) {
            uint4 va[4], vb[2];
#pragma unroll
            for (int mt = 0; mt < 4; mt++)
                va[mt] = lds128(sA + (uint32_t)(((wm * 4 + mt) * 4 + ks) * 512));
#pragma unroll
            for (int p = 0; p < 2; p++)
                vb[p] = lds128(sB + (uint32_t)(((wn * 2 + p) * 4 + ks) * 512));
#pragma unroll
            for (int mt = 0; mt < 4; mt++) {
                mma8(acc[mt][0], va[mt], vb[0].x, vb[0].z);
                mma8(acc[mt][1], va[mt], vb[0].y, vb[0].w);
                mma8(acc[mt][2], va[mt], vb[1].x, vb[1].z);
                mma8(acc[mt][3], va[mt], vb[1].y, vb[1].w);
            }
        }
        __syncthreads();
    }

    // store accumulators -> g_G
#pragma unroll
    for (int mt = 0; mt < 4; mt++) {
        const int row = blockIdx.x * 128 + wm * 64 + mt * 16 + gq;
#pragma unroll
        for (int nt = 0; nt < 4; nt++) {
            const int col = blockIdx.y * 128 + wn * 32 + nt * 8 + 2 * tq;
            *(float2*)&g_G[(size_t)row * 4096 + col] =
                make_float2(acc[mt][nt][0], acc[mt][nt][1]);
            *(float2*)&g_G[(size_t)(row + 8) * 4096 + col] =
                make_float2(acc[mt][nt][2], acc[mt][nt][3]);
        }
    }
}

// ---- epilogue: bias + activations + c/h update, writes 6 planes ----
__global__ void __launch_bounds__(256) lstm_epilogue(
    const float* __restrict__ c_prev,
    const float* __restrict__ bi, const float* __restrict__ bf,
    const float* __restrict__ bg, const float* __restrict__ bo,
    float* __restrict__ out, int nplanes)
{
    const int idx = blockIdx.x * 256 + threadIdx.x;   // float4 index over (m, h/4)
    const int m = idx >> 8;
    const int hh = (idx & 255) << 2;
    const float* gr = g_G + (size_t)m * 4096;

    float4 zi = *(const float4*)&gr[hh];
    float4 zf = *(const float4*)&gr[1024 + hh];
    float4 zg = *(const float4*)&gr[2048 + hh];
    float4 zo = *(const float4*)&gr[3072 + hh];
    float4 vbi = *(const float4*)&bi[hh];
    float4 vbf = *(const float4*)&bf[hh];
    float4 vbg = *(const float4*)&bg[hh];
    float4 vbo = *(const float4*)&bo[hh];
    float4 cp = *(const float4*)&c_prev[(size_t)m * HDIM + hh];

    float r[6][4];
    const float* pzi = &zi.x; const float* pzf = &zf.x;
    const float* pzg = &zg.x; const float* pzo = &zo.x;
    const float* pbi = &vbi.x; const float* pbf = &vbf.x;
    const float* pbg = &vbg.x; const float* pbo = &vbo.x;
    const float* pcp = &cp.x;
#pragma unroll
    for (int j = 0; j < 4; j++) {
        float vi = sigf(pzi[j] + pbi[j]);
        float vf = sigf(pzf[j] + pbf[j]);
        float vg = tanhf(pzg[j] + pbg[j]);
        float vo = sigf(pzo[j] + pbo[j]);
        float cc = vf * pcp[j] + vi * vg;
        r[0][j] = vo * tanhf(cc);
        r[1][j] = cc;
        r[2][j] = vi; r[3][j] = vf; r[4][j] = vg; r[5][j] = vo;
    }
    const size_t P = (size_t)BDIM * HDIM;
    float* o = out + (size_t)m * HDIM + hh;
#pragma unroll
    for (int pl = 0; pl < 6; pl++)
        if (pl < nplanes)
            *(float4*)(o + (size_t)pl * P) = *(const float4*)r[pl];
}

extern "C" void kernel_launch(void* const* d_in, const int* in_sizes, int n_in,
                              void* d_out, int out_size) {
    const float* x   = (const float*)d_in[0];
    const float* h   = (const float*)d_in[1];
    const float* c   = (const float*)d_in[2];
    const float* Wii = (const float*)d_in[3];  const float* bii = (const float*)d_in[4];
    const float* Wif = (const float*)d_in[5];  const float* bif = (const float*)d_in[6];
    const float* Wig = (const float*)d_in[7];  const float* big = (const float*)d_in[8];
    const float* Wio = (const float*)d_in[9];  const float* bio = (const float*)d_in[10];
    const float* Whi = (const float*)d_in[11]; const float* Whf = (const float*)d_in[12];
    const float* Whg = (const float*)d_in[13]; const float* Who = (const float*)d_in[14];

    cudaFuncSetAttribute(gemm_gates, cudaFuncAttributeMaxDynamicSharedMemorySize, SMEM_TOTAL);

    pack_A<<<8192, 256>>>(x, h);
    pack_B<<<8192, 256>>>(Wii, Wif, Wig, Wio, Whi, Whf, Whg, Who);

    dim3 grid(32, 32);
    gemm_gates<<<grid, 256, SMEM_TOTAL>>>();

    int np = out_size / (BDIM * HDIM);
    if (np > 6) np = 6;
    if (np < 1) np = 1;
    lstm_epilogue<<<(BDIM * HDIM / 4) / 256, 256>>>(c, bii, bif, big, bio, (float*)d_out, np);
}